// round 14
// baseline (speedup 1.0000x reference)
#include <cuda_runtime.h>
#include <cuda_bf16.h>
#include <cstdint>

#define NB 8
#define SEQ 2048
#define DH 1024
#define CT 64               // chunk length T
#define NCH (SEQ/CT)        // 32 chunks
#define LRATE 0.01f
#define C2 (2.0f/1024.0f)

// ---------------- scratch (static device globals; no allocation) -------------
__device__ float g_V[NB*SEQ*DH];
__device__ float g_W[NB*DH*DH];         // fp32 master inner weights
__device__ float g_A[NB*NCH*CT*CT];
__device__ float g_MT[NB*NCH*CT*CT];
__device__ float g_Ti[NB*NCH*CT*CT];
__device__ __nv_bfloat16 g_Xhi[NB*SEQ*DH];
__device__ __nv_bfloat16 g_Xlo[NB*SEQ*DH];
__device__ __nv_bfloat16 g_Thi[3*DH*DH];
__device__ __nv_bfloat16 g_Tlo[3*DH*DH];
__device__ __nv_bfloat16 g_Khi[NB*SEQ*DH];
__device__ __nv_bfloat16 g_Klo[NB*SEQ*DH];
__device__ __nv_bfloat16 g_Qhi[NB*SEQ*DH];
__device__ __nv_bfloat16 g_Qlo[NB*SEQ*DH];
__device__ __nv_bfloat16 g_Whi[NB*DH*DH];
__device__ __nv_bfloat16 g_Wlo[NB*DH*DH];

// ---------------- packed f32x2 helpers ---------------------------------------
typedef unsigned long long ull;
__device__ __forceinline__ void fma2(ull& c, ull a, ull b) {
    asm("fma.rn.f32x2 %0, %1, %2, %0;" : "+l"(c) : "l"(a), "l"(b));
}
__device__ __forceinline__ ull dupf(float a) {
    ull r; asm("mov.b64 %0, {%1, %1};" : "=l"(r) : "f"(a)); return r;
}
__device__ __forceinline__ float2 unpack2(ull v) {
    float2 f; asm("mov.b64 {%0, %1}, %2;" : "=f"(f.x), "=f"(f.y) : "l"(v)); return f;
}

// ---------------- mma.sync helpers -------------------------------------------
__device__ __forceinline__ uint32_t smem_u32(const void* p) {
    uint32_t a;
    asm("{ .reg .u64 t; cvta.to.shared.u64 t, %1; cvt.u32.u64 %0, t; }"
        : "=r"(a) : "l"(p));
    return a;
}
#define SW128(off) ((off) ^ (((off) >> 3) & 0x70))

__device__ __forceinline__ void ldsm_x4(uint32_t* r, uint32_t a) {
    asm volatile("ldmatrix.sync.aligned.m8n8.x4.shared.b16 {%0,%1,%2,%3}, [%4];"
                 : "=r"(r[0]), "=r"(r[1]), "=r"(r[2]), "=r"(r[3]) : "r"(a));
}
__device__ __forceinline__ void ldsm_x4t(uint32_t* r, uint32_t a) {
    asm volatile("ldmatrix.sync.aligned.m8n8.x4.trans.shared.b16 {%0,%1,%2,%3}, [%4];"
                 : "=r"(r[0]), "=r"(r[1]), "=r"(r[2]), "=r"(r[3]) : "r"(a));
}
__device__ __forceinline__ void mma16816(float* c, const uint32_t* a, const uint32_t* b) {
    asm volatile(
        "mma.sync.aligned.m16n8k16.row.col.f32.bf16.bf16.f32 "
        "{%0,%1,%2,%3}, {%4,%5,%6,%7}, {%8,%9}, {%0,%1,%2,%3};"
        : "+f"(c[0]), "+f"(c[1]), "+f"(c[2]), "+f"(c[3])
        : "r"(a[0]), "r"(a[1]), "r"(a[2]), "r"(a[3]), "r"(b[0]), "r"(b[1]));
}
__device__ __forceinline__ void cp16(uint32_t dst, const void* src) {
    asm volatile("cp.async.cg.shared.global [%0], [%1], 16;"
                 :: "r"(dst), "l"(src) : "memory");
}
#define CP_COMMIT() asm volatile("cp.async.commit_group;" ::: "memory")
#define CP_WAIT(n)  asm volatile("cp.async.wait_group %0;" :: "n"(n) : "memory")

// ---------------- convert inputs to bf16 hi/lo --------------------------------
__global__ void cvt_kernel(const float* __restrict__ X, const float* __restrict__ tK,
                           const float* __restrict__ tV, const float* __restrict__ tQ) {
    long i = (long)blockIdx.x * blockDim.x + threadIdx.x;
    if (i < (long)NB*SEQ*DH) {
        float x = X[i];
        __nv_bfloat16 h = __float2bfloat16(x);
        g_Xhi[i] = h;
        g_Xlo[i] = __float2bfloat16(x - __bfloat162float(h));
    }
    if (i < 3L*DH*DH) {
        int z = (int)(i / (DH*DH));
        long r = i - (long)z*DH*DH;
        const float* t = (z == 0) ? tK : (z == 1) ? tV : tQ;
        float x = t[r];
        __nv_bfloat16 h = __float2bfloat16(x);
        g_Thi[i] = h;
        g_Tlo[i] = __float2bfloat16(x - __bfloat162float(h));
    }
}

// ---------------- init: replicate W0 (+hi/lo) across batches -----------------
__global__ void init_state_kernel(const float* __restrict__ W0) {
    int i = blockIdx.x * blockDim.x + threadIdx.x;
    float w = W0[i];
    __nv_bfloat16 h = __float2bfloat16(w);
    __nv_bfloat16 l = __float2bfloat16(w - __bfloat162float(h));
    #pragma unroll
    for (int b = 0; b < NB; b++) {
        g_W  [(long)b*DH*DH + i] = w;
        g_Whi[(long)b*DH*DH + i] = h;
        g_Wlo[(long)b*DH*DH + i] = l;
    }
}

// ------------- mma.sync projection: C[16384,1024] = X @ Theta^T --------------
#define PSTG 49152
#define PROJ_SMEM (2*PSTG + 1024)

__global__ __launch_bounds__(256) void proj_mma_kernel() {
    extern __shared__ char psm[];
    uint32_t sb = (smem_u32(psm) + 1023u) & ~1023u;

    int tid = threadIdx.x, lane = tid & 31, wid = tid >> 5;
    int wm = (wid & 3) * 32, wn = (wid >> 2) * 32;
    long m0 = (long)blockIdx.x * 128;
    int  n0 = blockIdx.y * 64;
    int  z  = blockIdx.z;
    const __nv_bfloat16* Th = g_Thi + (long)z*DH*DH;
    const __nv_bfloat16* Tl = g_Tlo + (long)z*DH*DH;

    float c[2][4][4];
    #pragma unroll
    for (int im = 0; im < 2; im++)
        #pragma unroll
        for (int in = 0; in < 4; in++)
            #pragma unroll
            for (int k = 0; k < 4; k++) c[im][in][k] = 0.f;

    auto load_stage = [&](int ks, int st) {
        uint32_t base = sb + st*PSTG;
        int kb = ks * 64;
        #pragma unroll
        for (int p = 0; p < 4; p++) {
            int id = tid + p*256;
            int row = id >> 3, ch = id & 7;
            uint32_t off = SW128((uint32_t)(row*128 + ch*16));
            long g = (m0 + row)*DH + kb + ch*8;
            cp16(base + off,         g_Xhi + g);
            cp16(base + 16384 + off, g_Xlo + g);
        }
        #pragma unroll
        for (int p = 0; p < 4; p++) {
            int id = tid + p*256;
            int arr = id >> 9, rem = id & 511;
            int row = rem >> 3, ch = rem & 7;
            uint32_t off = SW128((uint32_t)(row*128 + ch*16));
            const __nv_bfloat16* src = (arr == 0) ? Th : Tl;
            cp16(base + 32768 + arr*8192 + off,
                 src + (long)(n0 + row)*DH + kb + ch*8);
        }
        CP_COMMIT();
    };

    load_stage(0, 0);
    for (int ks = 0; ks < 16; ks++) {
        int st = ks & 1;
        if (ks + 1 < 16) { load_stage(ks + 1, st ^ 1); CP_WAIT(1); }
        else             { CP_WAIT(0); }
        __syncthreads();

        uint32_t Ah = sb + st*PSTG, Al = Ah + 16384;
        uint32_t Bh = Ah + 32768,   Bl = Ah + 40960;
        #pragma unroll
        for (int kk = 0; kk < 4; kk++) {
            uint32_t ah[2][4], al[2][4], bh[2][4], bl[2][4];
            #pragma unroll
            for (int im = 0; im < 2; im++) {
                int t = lane >> 3, ri = lane & 7;
                int row = wm + im*16 + (t & 1)*8 + ri;
                uint32_t off = SW128((uint32_t)(row*128 + kk*32 + (t >> 1)*16));
                ldsm_x4(ah[im], Ah + off);
                ldsm_x4(al[im], Al + off);
            }
            #pragma unroll
            for (int ip = 0; ip < 2; ip++) {
                int g = lane >> 3, ri = lane & 7;
                int row = wn + ip*16 + (g >> 1)*8 + ri;
                uint32_t off = SW128((uint32_t)(row*128 + kk*32 + (g & 1)*16));
                ldsm_x4(bh[ip], Bh + off);
                ldsm_x4(bl[ip], Bl + off);
            }
            #pragma unroll
            for (int im = 0; im < 2; im++)
                #pragma unroll
                for (int ip = 0; ip < 2; ip++) {
                    mma16816(c[im][ip*2],   ah[im], &bh[ip][0]);
                    mma16816(c[im][ip*2+1], ah[im], &bh[ip][2]);
                    mma16816(c[im][ip*2],   al[im], &bh[ip][0]);
                    mma16816(c[im][ip*2+1], al[im], &bh[ip][2]);
                    mma16816(c[im][ip*2],   ah[im], &bl[ip][0]);
                    mma16816(c[im][ip*2+1], ah[im], &bl[ip][2]);
                }
        }
        __syncthreads();
    }

    // ---- epilogue: V fp32 (z==1); K/Q bf16 hi/lo (z!=1) ----
    __nv_bfloat16* Hout = (z == 0) ? g_Khi : g_Qhi;
    __nv_bfloat16* Lout = (z == 0) ? g_Klo : g_Qlo;
    int grp = lane >> 2, t4 = lane & 3;
    #pragma unroll
    for (int im = 0; im < 2; im++) {
        #pragma unroll
        for (int in = 0; in < 4; in++) {
            long row = m0 + wm + im*16 + grp;
            int col = n0 + wn + in*8 + t4*2;
            #pragma unroll
            for (int h = 0; h < 2; h++) {
                long idx = (row + h*8)*DH + col;
                float x0 = c[im][in][h*2], x1 = c[im][in][h*2+1];
                if (z == 1) {
                    *(float2*)(g_V + idx) = make_float2(x0, x1);
                } else {
                    __nv_bfloat16 h0 = __float2bfloat16(x0);
                    __nv_bfloat16 h1 = __float2bfloat16(x1);
                    __nv_bfloat162 hv; hv.x = h0; hv.y = h1;
                    __nv_bfloat162 lv;
                    lv.x = __float2bfloat16(x0 - __bfloat162float(h0));
                    lv.y = __float2bfloat16(x1 - __bfloat162float(h1));
                    *(__nv_bfloat162*)(Hout + idx) = hv;
                    *(__nv_bfloat162*)(Lout + idx) = lv;
                }
            }
        }
    }
}

// -------- mma.sync am: A = cA*([K]Kc^T+1); MT = LR*tril(Q Kc^T+1)^T ----------
#define AMSTG 32768
#define AM_SMEM (2*AMSTG + 1024)

__global__ __launch_bounds__(256) void am_mma_kernel() {
    extern __shared__ char amsm[];
    uint32_t sb = (smem_u32(amsm) + 1023u) & ~1023u;
    int c = blockIdx.x, b = blockIdx.y;
    const __nv_bfloat16* KhC = g_Khi + ((long)b*SEQ + c*CT)*DH;
    const __nv_bfloat16* KlC = g_Klo + ((long)b*SEQ + c*CT)*DH;
    const __nv_bfloat16* QhC = g_Qhi + ((long)b*SEQ + c*CT)*DH;
    const __nv_bfloat16* QlC = g_Qlo + ((long)b*SEQ + c*CT)*DH;
    float* Ao = g_A  + (((long)b*NCH + c)*CT)*CT;
    float* Mo = g_MT + (((long)b*NCH + c)*CT)*CT;

    int tid = threadIdx.x, lane = tid & 31, wid = tid >> 5;
    int wm = (wid & 3) * 32, wn = (wid >> 2) * 32;

    float cc[2][4][4];
    #pragma unroll
    for (int im = 0; im < 2; im++)
        #pragma unroll
        for (int in = 0; in < 4; in++)
            #pragma unroll
            for (int k = 0; k < 4; k++) cc[im][in][k] = 0.f;

    auto load_stage = [&](int ks, int st) {
        uint32_t base = sb + st*AMSTG;
        int kb = ks * 64;
        #pragma unroll
        for (int p = 0; p < 8; p++) {
            int id = tid + p*256;
            int arr = id >> 10, rem = id & 1023;
            int row = rem >> 3, ch = rem & 7;
            const __nv_bfloat16* src;
            if (arr == 0) src = (row < 64) ? (KhC + (long)row*DH) : (QhC + (long)(row-64)*DH);
            else          src = (row < 64) ? (KlC + (long)row*DH) : (QlC + (long)(row-64)*DH);
            cp16(base + arr*16384 + SW128((uint32_t)(row*128 + ch*16)),
                 src + kb + ch*8);
        }
        CP_COMMIT();
    };

    load_stage(0, 0);
    for (int ks = 0; ks < 16; ks++) {
        int st = ks & 1;
        if (ks + 1 < 16) { load_stage(ks + 1, st ^ 1); CP_WAIT(1); }
        else             { CP_WAIT(0); }
        __syncthreads();
        uint32_t Ah = sb + st*AMSTG, Al = Ah + 16384;
        #pragma unroll
        for (int kk = 0; kk < 4; kk++) {
            uint32_t ah[2][4], al[2][4], bh[2][4], bl[2][4];
            #pragma unroll
            for (int im = 0; im < 2; im++) {
                int t = lane >> 3, ri = lane & 7;
                int row = wm + im*16 + (t & 1)*8 + ri;
                uint32_t off = SW128((uint32_t)(row*128 + kk*32 + (t >> 1)*16));
                ldsm_x4(ah[im], Ah + off);
                ldsm_x4(al[im], Al + off);
            }
            #pragma unroll
            for (int ip = 0; ip < 2; ip++) {
                int g = lane >> 3, ri = lane & 7;
                int row = wn + ip*16 + (g >> 1)*8 + ri;   // rows 0..63 = Kc
                uint32_t off = SW128((uint32_t)(row*128 + kk*32 + (g & 1)*16));
                ldsm_x4(bh[ip], Ah + off);
                ldsm_x4(bl[ip], Al + off);
            }
            #pragma unroll
            for (int im = 0; im < 2; im++)
                #pragma unroll
                for (int ip = 0; ip < 2; ip++) {
                    mma16816(cc[im][ip*2],   ah[im], &bh[ip][0]);
                    mma16816(cc[im][ip*2+1], ah[im], &bh[ip][2]);
                    mma16816(cc[im][ip*2],   al[im], &bh[ip][0]);
                    mma16816(cc[im][ip*2+1], al[im], &bh[ip][2]);
                    mma16816(cc[im][ip*2],   ah[im], &bl[ip][0]);
                    mma16816(cc[im][ip*2+1], ah[im], &bl[ip][2]);
                }
        }
        __syncthreads();
    }

    const float cA = C2 * LRATE;
    int grp = lane >> 2, t4 = lane & 3;
    #pragma unroll
    for (int im = 0; im < 2; im++) {
        #pragma unroll
        for (int in = 0; in < 4; in++) {
            int s = wn + in*8 + t4*2;
            #pragma unroll
            for (int h = 0; h < 2; h++) {
                int t = wm + im*16 + grp + h*8;
                float v0 = cc[im][in][h*2]   + 1.f;
                float v1 = cc[im][in][h*2+1] + 1.f;
                if (t < 64) {
                    Ao[(long)t*CT + s]     = cA*v0;
                    Ao[(long)t*CT + s + 1] = cA*v1;
                } else {
                    int tp = t - 64;
                    Mo[(long)s*CT + tp]       = (s     <= tp) ? LRATE*v0 : 0.f;
                    Mo[(long)(s+1)*CT + tp]   = (s + 1 <= tp) ? LRATE*v1 : 0.f;
                }
            }
        }
    }
}

// -------- Tinv = (I + strict_lower(A))^{-1}, stored transposed [col][row] ----
__global__ __launch_bounds__(64) void tinv_kernel() {
    int c = blockIdx.x, b = blockIdx.y;
    const float* Ai = g_A  + (((long)b*NCH + c)*CT)*CT;
    float*       To = g_Ti + (((long)b*NCH + c)*CT)*CT;

    __shared__ float sL[CT*CT];
    __shared__ float X[CT*(CT+1)];
    int tid = threadIdx.x;
    for (int idx = tid; idx < CT*CT; idx += 64) sL[idx] = Ai[idx];
    #pragma unroll
    for (int s = 0; s < CT; s++) X[s*(CT+1) + tid] = (s == tid) ? 1.f : 0.f;
    __syncthreads();

    for (int i = 1; i < CT; i++) {
        float xi = 0.f;
        for (int s = 0; s < i; s++) xi -= sL[i*CT + s] * X[s*(CT+1) + tid];
        if (i > tid) X[i*(CT+1) + tid] = xi;
        __syncthreads();
    }
    for (int i = 0; i < CT; i++)
        To[(long)tid*CT + i] = X[i*(CT+1) + tid];
}

// ---------------- fused persistent chunk kernel (tensor-core) ----------------
#define OB_U   0u
#define OB_P   17408u
#define OB_G   34816u
#define OB_TI  52224u
#define OB_MT  69632u
#define OB_BS  87040u
#define OB_GTH 87296u
#define OB_GTL 95488u
#define OB_STG 104448u
#define ST1    49152u
#define K4ST   16384u
#define CH_SMEM (104448 + 2*49152)

__global__ __launch_bounds__(256) void chunk_fused_kernel(
    float* __restrict__ out, const float* __restrict__ b0) {
    extern __shared__ char smc[];
    float* smf = (float*)smc;
    float* U   = smf + OB_U/4;
    float* P   = smf + OB_P/4;
    float* G   = smf + OB_G/4;
    float* sTi = smf + OB_TI/4;
    float* sMT = smf + OB_MT/4;
    float* bsh = smf + OB_BS/4;
    uint32_t sb   = smem_u32(smc);
    uint32_t gth  = sb + OB_GTH;
    uint32_t gtl  = sb + OB_GTL;
    uint32_t stg  = sb + OB_STG;

    int b  = blockIdx.y;
    int r0 = blockIdx.x * 64;
    int tid = threadIdx.x;
    int lane = tid & 31, wid = tid >> 5;
    int tx = tid & 15, ty = tid >> 4;
    int grp = lane >> 2, t4 = lane & 3;

    float* Wp = g_W + ((long)b*DH + r0)*DH;
    __nv_bfloat16* WhiP = g_Whi + ((long)b*DH + r0)*DH;
    __nv_bfloat16* WloP = g_Wlo + ((long)b*DH + r0)*DH;
    if (tid < 64) bsh[tid] = b0[r0 + tid];
    __syncthreads();

    int wm = (wid & 3) * 32, wn = (wid >> 2) * 32;    // phase1 layout
    int wm4 = (wid & 3) * 16, wn4 = (wid >> 2) * 32;  // phase4 layout

    for (int c = 0; c < NCH; c++) {
        const __nv_bfloat16* KhC = g_Khi + ((long)b*SEQ + c*CT)*DH;
        const __nv_bfloat16* KlC = g_Klo + ((long)b*SEQ + c*CT)*DH;
        const __nv_bfloat16* QhC = g_Qhi + ((long)b*SEQ + c*CT)*DH;
        const __nv_bfloat16* QlC = g_Qlo + ((long)b*SEQ + c*CT)*DH;
        const float* Vc  = g_V  + ((long)b*SEQ + c*CT)*DH;
        const float* gTi = g_Ti + (((long)b*NCH + c)*CT)*CT;
        const float* gMT = g_MT + (((long)b*NCH + c)*CT)*CT;

        auto load_stage1 = [&](int ks, int st) {
            uint32_t base = stg + (uint32_t)st*ST1;
            int kb = ks * 64;
            #pragma unroll
            for (int p = 0; p < 8; p++) {
                int id = tid + p*256;
                int arr = id >> 10, rem = id & 1023;
                int row = rem >> 3, ch = rem & 7;
                const __nv_bfloat16* src;
                if (arr == 0) src = (row < 64) ? (KhC + (long)row*DH) : (QhC + (long)(row-64)*DH);
                else          src = (row < 64) ? (KlC + (long)row*DH) : (QlC + (long)(row-64)*DH);
                cp16(base + arr*16384 + SW128((uint32_t)(row*128 + ch*16)),
                     src + kb + ch*8);
            }
            #pragma unroll
            for (int p = 0; p < 4; p++) {
                int id = tid + p*256;
                int arr = id >> 9, rem = id & 511;
                int row = rem >> 3, ch = rem & 7;
                const __nv_bfloat16* src = (arr ? WloP : WhiP) + (long)row*DH + kb + ch*8;
                cp16(base + 32768 + arr*8192 + SW128((uint32_t)(row*128 + ch*16)), src);
            }
            CP_COMMIT();
        };

        // ---- Ti/MT prefetch: own cp.async group, hidden under phase 1 ----
        {
            #pragma unroll
            for (int p = 0; p < 8; p++) {
                int id = tid + p*256;              // 0..2047
                int arr = id >> 10, rem = id & 1023;
                int s = rem >> 4, j = rem & 15;
                const float* src = (arr ? gMT : gTi) + s*64 + j*4;
                uint32_t dst = sb + (arr ? OB_MT : OB_TI) + (uint32_t)(s*272 + j*16);
                cp16(dst, src);
            }
            CP_COMMIT();
        }

        // ---- phase 1: [U;P] = [Kc;Qc] @ Wslice^T via mma.sync ----
        float c1[2][4][4];
        #pragma unroll
        for (int im = 0; im < 2; im++)
            #pragma unroll
            for (int in = 0; in < 4; in++)
                #pragma unroll
                for (int k = 0; k < 4; k++) c1[im][in][k] = 0.f;

        load_stage1(0, 0);
        for (int ks = 0; ks < 16; ks++) {
            int st = ks & 1;
            if (ks + 1 < 16) { load_stage1(ks + 1, st ^ 1); CP_WAIT(1); }
            else             { CP_WAIT(0); }
            __syncthreads();
            uint32_t Ah = stg + (uint32_t)st*ST1, Al = Ah + 16384;
            uint32_t Bh = Ah + 32768,             Bl = Ah + 40960;
            #pragma unroll
            for (int kk = 0; kk < 4; kk++) {
                uint32_t ah[2][4], al[2][4], bh[2][4], bl[2][4];
                #pragma unroll
                for (int im = 0; im < 2; im++) {
                    int t = lane >> 3, ri = lane & 7;
                    int row = wm + im*16 + (t & 1)*8 + ri;
                    uint32_t off = SW128((uint32_t)(row*128 + kk*32 + (t >> 1)*16));
                    ldsm_x4(ah[im], Ah + off);
                    ldsm_x4(al[im], Al + off);
                }
                #pragma unroll
                for (int ip = 0; ip < 2; ip++) {
                    int g = lane >> 3, ri = lane & 7;
                    int row = wn + ip*16 + (g >> 1)*8 + ri;
                    uint32_t off = SW128((uint32_t)(row*128 + kk*32 + (g & 1)*16));
                    ldsm_x4(bh[ip], Bh + off);
                    ldsm_x4(bl[ip], Bl + off);
                }
                #pragma unroll
                for (int im = 0; im < 2; im++)
                    #pragma unroll
                    for (int ip = 0; ip < 2; ip++) {
                        mma16816(c1[im][ip*2],   ah[im], &bh[ip][0]);
                        mma16816(c1[im][ip*2+1], ah[im], &bh[ip][2]);
                        mma16816(c1[im][ip*2],   al[im], &bh[ip][0]);
                        mma16816(c1[im][ip*2+1], al[im], &bh[ip][2]);
                        mma16816(c1[im][ip*2],   ah[im], &bl[ip][0]);
                        mma16816(c1[im][ip*2+1], ah[im], &bl[ip][2]);
                    }
            }
            __syncthreads();
        }

        // ---- early phase-4 K prefetch (stage region is dead now) ----
        auto load_k = [&](int jt, int st) {
            uint32_t base = stg + (uint32_t)st*K4ST;
            #pragma unroll
            for (int p = 0; p < 4; p++) {
                int id = tid + p*256;
                int arr = id >> 9, rem = id & 511;
                int t_ = rem >> 3, ch = rem & 7;
                const __nv_bfloat16* src = (arr ? KlC : KhC) + (long)t_*DH + jt*64 + ch*8;
                cp16(base + arr*8192 + SW128((uint32_t)(t_*128 + ch*16)), src);
            }
            CP_COMMIT();
        };
        load_k(0, 0);
        load_k(1, 1);

        // ---- phase1 epilogue: U / P ----
        #pragma unroll
        for (int im = 0; im < 2; im++) {
            #pragma unroll
            for (int in = 0; in < 4; in++) {
                int rrow = wm + im*16 + grp;
                int n = wn + in*8 + t4*2;
                #pragma unroll
                for (int h = 0; h < 2; h++) {
                    int row2 = rrow + h*8;
                    float x0 = c1[im][in][h*2], x1 = c1[im][in][h*2+1];
                    if (row2 < 64) {
                        float2 vv = *(const float2*)(Vc + (long)row2*DH + r0 + n);
                        U[row2*68 + n]     = C2*(x0 + bsh[n]   - vv.x);
                        U[row2*68 + n + 1] = C2*(x1 + bsh[n+1] - vv.y);
                    } else {
                        P[(row2-64)*68 + n]     = x0 + bsh[n];
                        P[(row2-64)*68 + n + 1] = x1 + bsh[n+1];
                    }
                }
            }
        }
        __syncthreads();

        // ---- phase 2: G = Tinv @ U (f32x2) ----
        {
            ull ga[4][2];
            #pragma unroll
            for (int i = 0; i < 4; i++) { ga[i][0] = 0ull; ga[i][1] = 0ull; }
            #pragma unroll 4
            for (int s = 0; s < 64; s++) {
                float a[4];
                *(float4*)a = *(const float4*)(sTi + s*68 + ty*4);
                ulonglong2 bq = *(const ulonglong2*)(U + s*68 + tx*4);
                #pragma unroll
                for (int i = 0; i < 4; i++) {
                    ull aa = dupf(a[i]);
                    fma2(ga[i][0], aa, bq.x);
                    fma2(ga[i][1], aa, bq.y);
                }
            }
            #pragma unroll
            for (int i = 0; i < 4; i++) {
                int t = ty*4 + i;
                float2 c0 = unpack2(ga[i][0]), c1_ = unpack2(ga[i][1]);
                *(float4*)(G + t*68 + tx*4) = make_float4(c0.x, c0.y, c1_.x, c1_.y);
            }
        }
        __syncthreads();

        // ---- phase 3: out = P - M~ @ G (f32x2); Gt convert; bias ----
        {
            ull oa[4][2];
            #pragma unroll
            for (int i = 0; i < 4; i++) { oa[i][0] = 0ull; oa[i][1] = 0ull; }
            #pragma unroll 4
            for (int s = 0; s < 64; s++) {
                float a[4];
                *(float4*)a = *(const float4*)(sMT + s*68 + ty*4);
                ulonglong2 bq = *(const ulonglong2*)(G + s*68 + tx*4);
                #pragma unroll
                for (int i = 0; i < 4; i++) {
                    ull aa = dupf(a[i]);
                    fma2(oa[i][0], aa, bq.x);
                    fma2(oa[i][1], aa, bq.y);
                }
            }
            #pragma unroll
            for (int i = 0; i < 4; i++) {
                int t = ty*4 + i;
                float2 c0 = unpack2(oa[i][0]), c1_ = unpack2(oa[i][1]);
                float* op = out + ((long)b*SEQ + c*CT + t)*DH + r0 + tx*4;
                float4 pv = *(const float4*)(P + t*68 + tx*4);
                *(float4*)op = make_float4(pv.x - c0.x, pv.y - c0.y,
                                           pv.z - c1_.x, pv.w - c1_.y);
            }
            for (int idx = tid; idx < CT*CT; idx += 256) {
                int t_ = idx >> 6, r_ = idx & 63;
                float g = G[t_*68 + r_];
                __nv_bfloat16 h = __float2bfloat16(g);
                float hf = __bfloat162float(h);
                __nv_bfloat16 l = __float2bfloat16(g - hf);
                uint32_t off = SW128((uint32_t)(r_*128 + t_*2));
                *(__nv_bfloat16*)(smc + OB_GTH + off) = h;
                *(__nv_bfloat16*)(smc + OB_GTL + off) = l;
            }
            if (tid < 64) {
                float sumg = 0.f;
                #pragma unroll 8
                for (int t = 0; t < 64; t++) sumg += G[t*68 + tid];
                bsh[tid] -= LRATE * sumg;
            }
        }
        __syncthreads();

        // ---- phase 4: Wslice -= LR * G^T @ Kc (mma.sync, 3-buffer pipeline) --
        uint32_t afh[4][4], afl[4][4];
        #pragma unroll
        for (int kk = 0; kk < 4; kk++) {
            int t = lane >> 3, ri = lane & 7;
            int row = wm4 + (t & 1)*8 + ri;
            uint32_t off = SW128((uint32_t)(row*128 + kk*32 + (t >> 1)*16));
            ldsm_x4(afh[kk], gth + off);
            ldsm_x4(afl[kk], gtl + off);
        }

        for (int jt = 0; jt < 16; jt++) {
            int st = jt % 3;
            if (jt + 1 < 16) { CP_WAIT(1); } else { CP_WAIT(0); }
            __syncthreads();
            if (jt + 2 < 16) load_k(jt + 2, (jt + 2) % 3);

            float c4[4][4];
            #pragma unroll
            for (int in = 0; in < 4; in++)
                #pragma unroll
                for (int k = 0; k < 4; k++) c4[in][k] = 0.f;
            uint32_t Kh = stg + (uint32_t)st*K4ST, Kl = Kh + 8192;
            #pragma unroll
            for (int kk = 0; kk < 4; kk++) {
                uint32_t bh[2][4], bl[2][4];
                #pragma unroll
                for (int ip = 0; ip < 2; ip++) {
                    int g = lane >> 3;
                    int row = kk*16 + (g & 1)*8 + (lane & 7);
                    uint32_t off = SW128((uint32_t)(row*128 + (wn4 + (ip*2 + (g >> 1))*8)*2));
                    ldsm_x4t(bh[ip], Kh + off);
                    ldsm_x4t(bl[ip], Kl + off);
                }
                #pragma unroll
                for (int ip = 0; ip < 2; ip++)
                    #pragma unroll
                    for (int q = 0; q < 2; q++) {
                        int in = ip*2 + q;
                        mma16816(c4[in], afh[kk], &bh[ip][q*2]);
                        mma16816(c4[in], afl[kk], &bh[ip][q*2]);
                        mma16816(c4[in], afh[kk], &bl[ip][q*2]);
                    }
            }
            // epilogue: RMW fp32 W + refresh bf16 hi/lo
            #pragma unroll
            for (int in = 0; in < 4; in++) {
                int colg = jt*64 + wn4 + in*8 + t4*2;
                #pragma unroll
                for (int h = 0; h < 2; h++) {
                    int rw = wm4 + grp + h*8;
                    long idx = (long)rw*DH + colg;
                    float2 w = *(float2*)(Wp + idx);
                    w.x -= LRATE * c4[in][h*2+0];
                    w.y -= LRATE * c4[in][h*2+1];
                    *(float2*)(Wp + idx) = w;
                    __nv_bfloat16 h0 = __float2bfloat16(w.x);
                    __nv_bfloat16 h1 = __float2bfloat16(w.y);
                    __nv_bfloat162 hv; hv.x = h0; hv.y = h1;
                    __nv_bfloat162 lv;
                    lv.x = __float2bfloat16(w.x - __bfloat162float(h0));
                    lv.y = __float2bfloat16(w.y - __bfloat162float(h1));
                    *(__nv_bfloat162*)(WhiP + idx) = hv;
                    *(__nv_bfloat162*)(WloP + idx) = lv;
                }
            }
        }
        __syncthreads();
    }
}

// ---------------- launch ------------------------------------------------------
extern "C" void kernel_launch(void* const* d_in, const int* in_sizes, int n_in,
                              void* d_out, int out_size) {
    const float* in_seq = (const float*)d_in[0];
    const float* tK = (const float*)d_in[1];
    const float* tV = (const float*)d_in[2];
    const float* tQ = (const float*)d_in[3];
    const float* W0 = (const float*)d_in[4];
    const float* b0 = (const float*)d_in[5];
    float* out = (float*)d_out;

    cudaFuncSetAttribute(chunk_fused_kernel,
                         cudaFuncAttributeMaxDynamicSharedMemorySize, CH_SMEM);
    cudaFuncSetAttribute(proj_mma_kernel,
                         cudaFuncAttributeMaxDynamicSharedMemorySize, PROJ_SMEM);
    cudaFuncSetAttribute(am_mma_kernel,
                         cudaFuncAttributeMaxDynamicSharedMemorySize, AM_SMEM);

    cvt_kernel<<<(NB*SEQ*DH)/256, 256>>>(in_seq, tK, tV, tQ);
    init_state_kernel<<<(DH*DH)/256, 256>>>(W0);
    proj_mma_kernel<<<dim3((NB*SEQ)/128, DH/64, 3), 256, PROJ_SMEM>>>();
    am_mma_kernel<<<dim3(NCH, NB), 256, AM_SMEM>>>();
    tinv_kernel<<<dim3(NCH, NB), 64>>>();
    chunk_fused_kernel<<<dim3(DH/64, NB), 256, CH_SMEM>>>(out, b0);
}

// round 15
// speedup vs baseline: 1.4426x; 1.4426x over previous
#include <cuda_runtime.h>
#include <cuda_bf16.h>
#include <cstdint>

#define NB 8
#define SEQ 2048
#define DH 1024
#define CT 64               // chunk length T
#define NCH (SEQ/CT)        // 32 chunks
#define LRATE 0.01f
#define C2 (2.0f/1024.0f)

// ---------------- scratch (static device globals; no allocation) -------------
__device__ float g_V[NB*SEQ*DH];
__device__ float g_W[NB*DH*DH];         // fp32 master inner weights
__device__ float g_A[NB*NCH*CT*CT];
__device__ float g_MT[NB*NCH*CT*CT];
__device__ float g_Ti[NB*NCH*CT*CT];
__device__ __nv_bfloat16 g_Xhi[NB*SEQ*DH];
__device__ __nv_bfloat16 g_Xlo[NB*SEQ*DH];
__device__ __nv_bfloat16 g_Thi[3*DH*DH];
__device__ __nv_bfloat16 g_Tlo[3*DH*DH];
__device__ __nv_bfloat16 g_Khi[NB*SEQ*DH];
__device__ __nv_bfloat16 g_Klo[NB*SEQ*DH];
__device__ __nv_bfloat16 g_Qhi[NB*SEQ*DH];
__device__ __nv_bfloat16 g_Qlo[NB*SEQ*DH];
__device__ __nv_bfloat16 g_Whi[NB*DH*DH];   // used only for chunk-0 phase 1
__device__ __nv_bfloat16 g_Wlo[NB*DH*DH];

// ---------------- packed f32x2 helpers ---------------------------------------
typedef unsigned long long ull;
__device__ __forceinline__ void fma2(ull& c, ull a, ull b) {
    asm("fma.rn.f32x2 %0, %1, %2, %0;" : "+l"(c) : "l"(a), "l"(b));
}
__device__ __forceinline__ ull dupf(float a) {
    ull r; asm("mov.b64 %0, {%1, %1};" : "=l"(r) : "f"(a)); return r;
}
__device__ __forceinline__ float2 unpack2(ull v) {
    float2 f; asm("mov.b64 {%0, %1}, %2;" : "=f"(f.x), "=f"(f.y) : "l"(v)); return f;
}

// ---------------- mma.sync helpers -------------------------------------------
__device__ __forceinline__ uint32_t smem_u32(const void* p) {
    uint32_t a;
    asm("{ .reg .u64 t; cvta.to.shared.u64 t, %1; cvt.u32.u64 %0, t; }"
        : "=r"(a) : "l"(p));
    return a;
}
#define SW128(off) ((off) ^ (((off) >> 3) & 0x70))

__device__ __forceinline__ void ldsm_x4(uint32_t* r, uint32_t a) {
    asm volatile("ldmatrix.sync.aligned.m8n8.x4.shared.b16 {%0,%1,%2,%3}, [%4];"
                 : "=r"(r[0]), "=r"(r[1]), "=r"(r[2]), "=r"(r[3]) : "r"(a));
}
__device__ __forceinline__ void ldsm_x4t(uint32_t* r, uint32_t a) {
    asm volatile("ldmatrix.sync.aligned.m8n8.x4.trans.shared.b16 {%0,%1,%2,%3}, [%4];"
                 : "=r"(r[0]), "=r"(r[1]), "=r"(r[2]), "=r"(r[3]) : "r"(a));
}
__device__ __forceinline__ void mma16816(float* c, const uint32_t* a, const uint32_t* b) {
    asm volatile(
        "mma.sync.aligned.m16n8k16.row.col.f32.bf16.bf16.f32 "
        "{%0,%1,%2,%3}, {%4,%5,%6,%7}, {%8,%9}, {%0,%1,%2,%3};"
        : "+f"(c[0]), "+f"(c[1]), "+f"(c[2]), "+f"(c[3])
        : "r"(a[0]), "r"(a[1]), "r"(a[2]), "r"(a[3]), "r"(b[0]), "r"(b[1]));
}
__device__ __forceinline__ void cp16(uint32_t dst, const void* src) {
    asm volatile("cp.async.cg.shared.global [%0], [%1], 16;"
                 :: "r"(dst), "l"(src) : "memory");
}
#define CP_COMMIT() asm volatile("cp.async.commit_group;" ::: "memory")
#define CP_WAIT(n)  asm volatile("cp.async.wait_group %0;" :: "n"(n) : "memory")

// ---------------- convert inputs to bf16 hi/lo --------------------------------
__global__ void cvt_kernel(const float* __restrict__ X, const float* __restrict__ tK,
                           const float* __restrict__ tV, const float* __restrict__ tQ) {
    long i = (long)blockIdx.x * blockDim.x + threadIdx.x;
    if (i < (long)NB*SEQ*DH) {
        float x = X[i];
        __nv_bfloat16 h = __float2bfloat16(x);
        g_Xhi[i] = h;
        g_Xlo[i] = __float2bfloat16(x - __bfloat162float(h));
    }
    if (i < 3L*DH*DH) {
        int z = (int)(i / (DH*DH));
        long r = i - (long)z*DH*DH;
        const float* t = (z == 0) ? tK : (z == 1) ? tV : tQ;
        float x = t[r];
        __nv_bfloat16 h = __float2bfloat16(x);
        g_Thi[i] = h;
        g_Tlo[i] = __float2bfloat16(x - __bfloat162float(h));
    }
}

// ---------------- init: replicate W0 (+hi/lo) across batches -----------------
__global__ void init_state_kernel(const float* __restrict__ W0) {
    int i = blockIdx.x * blockDim.x + threadIdx.x;
    float w = W0[i];
    __nv_bfloat16 h = __float2bfloat16(w);
    __nv_bfloat16 l = __float2bfloat16(w - __bfloat162float(h));
    #pragma unroll
    for (int b = 0; b < NB; b++) {
        g_W  [(long)b*DH*DH + i] = w;
        g_Whi[(long)b*DH*DH + i] = h;
        g_Wlo[(long)b*DH*DH + i] = l;
    }
}

// ------------- mma.sync projection: C[16384,1024] = X @ Theta^T --------------
#define PSTG 49152
#define PROJ_SMEM (2*PSTG + 1024)

__global__ __launch_bounds__(256) void proj_mma_kernel() {
    extern __shared__ char psm[];
    uint32_t sb = (smem_u32(psm) + 1023u) & ~1023u;

    int tid = threadIdx.x, lane = tid & 31, wid = tid >> 5;
    int wm = (wid & 3) * 32, wn = (wid >> 2) * 32;
    long m0 = (long)blockIdx.x * 128;
    int  n0 = blockIdx.y * 64;
    int  z  = blockIdx.z;
    const __nv_bfloat16* Th = g_Thi + (long)z*DH*DH;
    const __nv_bfloat16* Tl = g_Tlo + (long)z*DH*DH;

    float c[2][4][4];
    #pragma unroll
    for (int im = 0; im < 2; im++)
        #pragma unroll
        for (int in = 0; in < 4; in++)
            #pragma unroll
            for (int k = 0; k < 4; k++) c[im][in][k] = 0.f;

    auto load_stage = [&](int ks, int st) {
        uint32_t base = sb + st*PSTG;
        int kb = ks * 64;
        #pragma unroll
        for (int p = 0; p < 4; p++) {
            int id = tid + p*256;
            int row = id >> 3, ch = id & 7;
            uint32_t off = SW128((uint32_t)(row*128 + ch*16));
            long g = (m0 + row)*DH + kb + ch*8;
            cp16(base + off,         g_Xhi + g);
            cp16(base + 16384 + off, g_Xlo + g);
        }
        #pragma unroll
        for (int p = 0; p < 4; p++) {
            int id = tid + p*256;
            int arr = id >> 9, rem = id & 511;
            int row = rem >> 3, ch = rem & 7;
            uint32_t off = SW128((uint32_t)(row*128 + ch*16));
            const __nv_bfloat16* src = (arr == 0) ? Th : Tl;
            cp16(base + 32768 + arr*8192 + off,
                 src + (long)(n0 + row)*DH + kb + ch*8);
        }
        CP_COMMIT();
    };

    load_stage(0, 0);
    for (int ks = 0; ks < 16; ks++) {
        int st = ks & 1;
        if (ks + 1 < 16) { load_stage(ks + 1, st ^ 1); CP_WAIT(1); }
        else             { CP_WAIT(0); }
        __syncthreads();

        uint32_t Ah = sb + st*PSTG, Al = Ah + 16384;
        uint32_t Bh = Ah + 32768,   Bl = Ah + 40960;
        #pragma unroll
        for (int kk = 0; kk < 4; kk++) {
            uint32_t ah[2][4], al[2][4], bh[2][4], bl[2][4];
            #pragma unroll
            for (int im = 0; im < 2; im++) {
                int t = lane >> 3, ri = lane & 7;
                int row = wm + im*16 + (t & 1)*8 + ri;
                uint32_t off = SW128((uint32_t)(row*128 + kk*32 + (t >> 1)*16));
                ldsm_x4(ah[im], Ah + off);
                ldsm_x4(al[im], Al + off);
            }
            #pragma unroll
            for (int ip = 0; ip < 2; ip++) {
                int g = lane >> 3, ri = lane & 7;
                int row = wn + ip*16 + (g >> 1)*8 + ri;
                uint32_t off = SW128((uint32_t)(row*128 + kk*32 + (g & 1)*16));
                ldsm_x4(bh[ip], Bh + off);
                ldsm_x4(bl[ip], Bl + off);
            }
            #pragma unroll
            for (int im = 0; im < 2; im++)
                #pragma unroll
                for (int ip = 0; ip < 2; ip++) {
                    mma16816(c[im][ip*2],   ah[im], &bh[ip][0]);
                    mma16816(c[im][ip*2+1], ah[im], &bh[ip][2]);
                    mma16816(c[im][ip*2],   al[im], &bh[ip][0]);
                    mma16816(c[im][ip*2+1], al[im], &bh[ip][2]);
                    mma16816(c[im][ip*2],   ah[im], &bl[ip][0]);
                    mma16816(c[im][ip*2+1], ah[im], &bl[ip][2]);
                }
        }
        __syncthreads();
    }

    __nv_bfloat16* Hout = (z == 0) ? g_Khi : g_Qhi;
    __nv_bfloat16* Lout = (z == 0) ? g_Klo : g_Qlo;
    int grp = lane >> 2, t4 = lane & 3;
    #pragma unroll
    for (int im = 0; im < 2; im++) {
        #pragma unroll
        for (int in = 0; in < 4; in++) {
            long row = m0 + wm + im*16 + grp;
            int col = n0 + wn + in*8 + t4*2;
            #pragma unroll
            for (int h = 0; h < 2; h++) {
                long idx = (row + h*8)*DH + col;
                float x0 = c[im][in][h*2], x1 = c[im][in][h*2+1];
                if (z == 1) {
                    *(float2*)(g_V + idx) = make_float2(x0, x1);
                } else {
                    __nv_bfloat16 h0 = __float2bfloat16(x0);
                    __nv_bfloat16 h1 = __float2bfloat16(x1);
                    __nv_bfloat162 hv; hv.x = h0; hv.y = h1;
                    __nv_bfloat162 lv;
                    lv.x = __float2bfloat16(x0 - __bfloat162float(h0));
                    lv.y = __float2bfloat16(x1 - __bfloat162float(h1));
                    *(__nv_bfloat162*)(Hout + idx) = hv;
                    *(__nv_bfloat162*)(Lout + idx) = lv;
                }
            }
        }
    }
}

// -------- mma.sync am: A = cA*([K]Kc^T+1); MT = LR*tril(Q Kc^T+1)^T ----------
#define AMSTG 32768
#define AM_SMEM (2*AMSTG + 1024)

__global__ __launch_bounds__(256) void am_mma_kernel() {
    extern __shared__ char amsm[];
    uint32_t sb = (smem_u32(amsm) + 1023u) & ~1023u;
    int c = blockIdx.x, b = blockIdx.y;
    const __nv_bfloat16* KhC = g_Khi + ((long)b*SEQ + c*CT)*DH;
    const __nv_bfloat16* KlC = g_Klo + ((long)b*SEQ + c*CT)*DH;
    const __nv_bfloat16* QhC = g_Qhi + ((long)b*SEQ + c*CT)*DH;
    const __nv_bfloat16* QlC = g_Qlo + ((long)b*SEQ + c*CT)*DH;
    float* Ao = g_A  + (((long)b*NCH + c)*CT)*CT;
    float* Mo = g_MT + (((long)b*NCH + c)*CT)*CT;

    int tid = threadIdx.x, lane = tid & 31, wid = tid >> 5;
    int wm = (wid & 3) * 32, wn = (wid >> 2) * 32;

    float cc[2][4][4];
    #pragma unroll
    for (int im = 0; im < 2; im++)
        #pragma unroll
        for (int in = 0; in < 4; in++)
            #pragma unroll
            for (int k = 0; k < 4; k++) cc[im][in][k] = 0.f;

    auto load_stage = [&](int ks, int st) {
        uint32_t base = sb + st*AMSTG;
        int kb = ks * 64;
        #pragma unroll
        for (int p = 0; p < 8; p++) {
            int id = tid + p*256;
            int arr = id >> 10, rem = id & 1023;
            int row = rem >> 3, ch = rem & 7;
            const __nv_bfloat16* src;
            if (arr == 0) src = (row < 64) ? (KhC + (long)row*DH) : (QhC + (long)(row-64)*DH);
            else          src = (row < 64) ? (KlC + (long)row*DH) : (QlC + (long)(row-64)*DH);
            cp16(base + arr*16384 + SW128((uint32_t)(row*128 + ch*16)),
                 src + kb + ch*8);
        }
        CP_COMMIT();
    };

    load_stage(0, 0);
    for (int ks = 0; ks < 16; ks++) {
        int st = ks & 1;
        if (ks + 1 < 16) { load_stage(ks + 1, st ^ 1); CP_WAIT(1); }
        else             { CP_WAIT(0); }
        __syncthreads();
        uint32_t Ah = sb + st*AMSTG, Al = Ah + 16384;
        #pragma unroll
        for (int kk = 0; kk < 4; kk++) {
            uint32_t ah[2][4], al[2][4], bh[2][4], bl[2][4];
            #pragma unroll
            for (int im = 0; im < 2; im++) {
                int t = lane >> 3, ri = lane & 7;
                int row = wm + im*16 + (t & 1)*8 + ri;
                uint32_t off = SW128((uint32_t)(row*128 + kk*32 + (t >> 1)*16));
                ldsm_x4(ah[im], Ah + off);
                ldsm_x4(al[im], Al + off);
            }
            #pragma unroll
            for (int ip = 0; ip < 2; ip++) {
                int g = lane >> 3, ri = lane & 7;
                int row = wn + ip*16 + (g >> 1)*8 + ri;
                uint32_t off = SW128((uint32_t)(row*128 + kk*32 + (g & 1)*16));
                ldsm_x4(bh[ip], Ah + off);
                ldsm_x4(bl[ip], Al + off);
            }
            #pragma unroll
            for (int im = 0; im < 2; im++)
                #pragma unroll
                for (int ip = 0; ip < 2; ip++) {
                    mma16816(cc[im][ip*2],   ah[im], &bh[ip][0]);
                    mma16816(cc[im][ip*2+1], ah[im], &bh[ip][2]);
                    mma16816(cc[im][ip*2],   al[im], &bh[ip][0]);
                    mma16816(cc[im][ip*2+1], al[im], &bh[ip][2]);
                    mma16816(cc[im][ip*2],   ah[im], &bl[ip][0]);
                    mma16816(cc[im][ip*2+1], ah[im], &bl[ip][2]);
                }
        }
        __syncthreads();
    }

    const float cA = C2 * LRATE;
    int grp = lane >> 2, t4 = lane & 3;
    #pragma unroll
    for (int im = 0; im < 2; im++) {
        #pragma unroll
        for (int in = 0; in < 4; in++) {
            int s = wn + in*8 + t4*2;
            #pragma unroll
            for (int h = 0; h < 2; h++) {
                int t = wm + im*16 + grp + h*8;
                float v0 = cc[im][in][h*2]   + 1.f;
                float v1 = cc[im][in][h*2+1] + 1.f;
                if (t < 64) {
                    Ao[(long)t*CT + s]     = cA*v0;
                    Ao[(long)t*CT + s + 1] = cA*v1;
                } else {
                    int tp = t - 64;
                    Mo[(long)s*CT + tp]       = (s     <= tp) ? LRATE*v0 : 0.f;
                    Mo[(long)(s+1)*CT + tp]   = (s + 1 <= tp) ? LRATE*v1 : 0.f;
                }
            }
        }
    }
}

// -------- Tinv = (I + strict_lower(A))^{-1}, stored transposed [col][row] ----
__global__ __launch_bounds__(64) void tinv_kernel() {
    int c = blockIdx.x, b = blockIdx.y;
    const float* Ai = g_A  + (((long)b*NCH + c)*CT)*CT;
    float*       To = g_Ti + (((long)b*NCH + c)*CT)*CT;

    __shared__ float sL[CT*CT];
    __shared__ float X[CT*(CT+1)];
    int tid = threadIdx.x;
    for (int idx = tid; idx < CT*CT; idx += 64) sL[idx] = Ai[idx];
    #pragma unroll
    for (int s = 0; s < CT; s++) X[s*(CT+1) + tid] = (s == tid) ? 1.f : 0.f;
    __syncthreads();

    for (int i = 1; i < CT; i++) {
        float xi = 0.f;
        for (int s = 0; s < i; s++) xi -= sL[i*CT + s] * X[s*(CT+1) + tid];
        if (i > tid) X[i*(CT+1) + tid] = xi;
        __syncthreads();
    }
    for (int i = 0; i < CT; i++)
        To[(long)tid*CT + i] = X[i*(CT+1) + tid];
}

// ---------------- fused persistent chunk kernel: ph4(c) ∥ ph1(c+1) -----------
// smem map (bytes):
//   sTi 0 (17408) | sMT 17408 (17408) | GtH 34816 (8192) | GtL 43008 (8192)
//   bsh 51200 (256)
//   KQ stages 51456 (3 x 32768)          [A operand: [K;Q] hi/lo, next chunk]
//   K4 bufs 149760 (3 x 16384)           [ph4 B operand; U/P alias here]
//   Wst 198912 (2 x 16384)               [ph1 B operand: W hi/lo handoff; G alias]
#define OB_TI   0u
#define OB_MT   17408u
#define OB_GTH  34816u
#define OB_GTL  43008u
#define OB_BS   51200u
#define OB_KQ   51456u
#define OB_K4   149760u
#define OB_WST  198912u
#define CH_SMEM 231680

__global__ __launch_bounds__(256) void chunk_fused_kernel(
    float* __restrict__ out, const float* __restrict__ b0) {
    extern __shared__ char smc[];
    float* smf = (float*)smc;
    float* sTi = smf + OB_TI/4;
    float* sMT = smf + OB_MT/4;
    float* bsh = smf + OB_BS/4;
    float* U   = smf + OB_K4/4;          // alias K4 region (dead in ph1-3)
    float* P   = U + 4352;
    float* G   = smf + OB_WST/4;         // alias Wst region (dead in ph1-3)
    uint32_t sb  = smem_u32(smc);
    uint32_t gth = sb + OB_GTH;
    uint32_t gtl = sb + OB_GTL;

    int b  = blockIdx.y;
    int r0 = blockIdx.x * 64;
    int tid = threadIdx.x;
    int lane = tid & 31, wid = tid >> 5;
    int tx = tid & 15, ty = tid >> 4;
    int grp = lane >> 2, t4 = lane & 3;

    float* Wp = g_W + ((long)b*DH + r0)*DH;
    const __nv_bfloat16* WhiP = g_Whi + ((long)b*DH + r0)*DH;
    const __nv_bfloat16* WloP = g_Wlo + ((long)b*DH + r0)*DH;
    if (tid < 64) bsh[tid] = b0[r0 + tid];
    __syncthreads();

    int wm = (wid & 3) * 32, wn = (wid >> 2) * 32;    // ph1 layout
    int wm4 = (wid & 3) * 16, wn4 = (wid >> 2) * 32;  // ph4 layout

    float c1[2][4][4];
    uint32_t afh[4][4], afl[4][4];
    #pragma unroll
    for (int im = 0; im < 2; im++)
        #pragma unroll
        for (int in = 0; in < 4; in++)
            #pragma unroll
            for (int k = 0; k < 4; k++) c1[im][in][k] = 0.f;

    // ---- shared building blocks ----
    auto load_kq = [&](const __nv_bfloat16* Kh, const __nv_bfloat16* Kl,
                       const __nv_bfloat16* Qh, const __nv_bfloat16* Ql,
                       int ks, int buf) {           // no commit
        uint32_t base = sb + OB_KQ + (uint32_t)buf*32768u;
        int kb = ks * 64;
        #pragma unroll
        for (int p = 0; p < 8; p++) {
            int id = tid + p*256;
            int arr = id >> 10, rem = id & 1023;
            int row = rem >> 3, ch = rem & 7;
            const __nv_bfloat16* src;
            if (arr == 0) src = (row < 64) ? (Kh + (long)row*DH) : (Qh + (long)(row-64)*DH);
            else          src = (row < 64) ? (Kl + (long)row*DH) : (Ql + (long)(row-64)*DH);
            cp16(base + arr*16384 + SW128((uint32_t)(row*128 + ch*16)),
                 src + kb + ch*8);
        }
    };
    auto load_k4 = [&](const __nv_bfloat16* Kh, const __nv_bfloat16* Kl,
                       int jt, int buf) {           // no commit
        uint32_t base = sb + OB_K4 + (uint32_t)buf*16384u;
        #pragma unroll
        for (int p = 0; p < 4; p++) {
            int id = tid + p*256;
            int arr = id >> 9, rem = id & 511;
            int t_ = rem >> 3, ch = rem & 7;
            const __nv_bfloat16* src = (arr ? Kl : Kh) + (long)t_*DH + jt*64 + ch*8;
            cp16(base + arr*8192 + SW128((uint32_t)(t_*128 + ch*16)), src);
        }
    };
    auto ph1_step = [&](uint32_t Ah, uint32_t Bh) {  // A: KQ buf; B: W tile (hi|lo@+8192)
        uint32_t Al = Ah + 16384, Bl = Bh + 8192;
        #pragma unroll
        for (int kk = 0; kk < 4; kk++) {
            uint32_t ah[2][4], al[2][4], bh[2][4], bl[2][4];
            #pragma unroll
            for (int im = 0; im < 2; im++) {
                int t = lane >> 3, ri = lane & 7;
                int row = wm + im*16 + (t & 1)*8 + ri;
                uint32_t off = SW128((uint32_t)(row*128 + kk*32 + (t >> 1)*16));
                ldsm_x4(ah[im], Ah + off);
                ldsm_x4(al[im], Al + off);
            }
            #pragma unroll
            for (int ip = 0; ip < 2; ip++) {
                int g = lane >> 3, ri = lane & 7;
                int row = wn + ip*16 + (g >> 1)*8 + ri;
                uint32_t off = SW128((uint32_t)(row*128 + kk*32 + (g & 1)*16));
                ldsm_x4(bh[ip], Bh + off);
                ldsm_x4(bl[ip], Bl + off);
            }
            #pragma unroll
            for (int im = 0; im < 2; im++)
                #pragma unroll
                for (int ip = 0; ip < 2; ip++) {
                    mma16816(c1[im][ip*2],   ah[im], &bh[ip][0]);
                    mma16816(c1[im][ip*2+1], ah[im], &bh[ip][2]);
                    mma16816(c1[im][ip*2],   al[im], &bh[ip][0]);
                    mma16816(c1[im][ip*2+1], al[im], &bh[ip][2]);
                    mma16816(c1[im][ip*2],   ah[im], &bl[ip][0]);
                    mma16816(c1[im][ip*2+1], ah[im], &bl[ip][2]);
                }
        }
    };
    auto ph4_step = [&](uint32_t Kh, float (&c4)[4][4]) {
        uint32_t Kl = Kh + 8192;
        #pragma unroll
        for (int in = 0; in < 4; in++)
            #pragma unroll
            for (int k = 0; k < 4; k++) c4[in][k] = 0.f;
        #pragma unroll
        for (int kk = 0; kk < 4; kk++) {
            uint32_t bh[2][4], bl[2][4];
            #pragma unroll
            for (int ip = 0; ip < 2; ip++) {
                int g = lane >> 3;
                int row = kk*16 + (g & 1)*8 + (lane & 7);
                uint32_t off = SW128((uint32_t)(row*128 + (wn4 + (ip*2 + (g >> 1))*8)*2));
                ldsm_x4t(bh[ip], Kh + off);
                ldsm_x4t(bl[ip], Kl + off);
            }
            #pragma unroll
            for (int ip = 0; ip < 2; ip++)
                #pragma unroll
                for (int q = 0; q < 2; q++) {
                    int in = ip*2 + q;
                    mma16816(c4[in], afh[kk], &bh[ip][q*2]);
                    mma16816(c4[in], afl[kk], &bh[ip][q*2]);
                    mma16816(c4[in], afh[kk], &bl[ip][q*2]);
                }
        }
    };

    // ---- prologue: chunk-0 phase 1, W from global mirrors ----
    {
        const __nv_bfloat16* Kh0 = g_Khi + (long)b*SEQ*DH;
        const __nv_bfloat16* Kl0 = g_Klo + (long)b*SEQ*DH;
        const __nv_bfloat16* Qh0 = g_Qhi + (long)b*SEQ*DH;
        const __nv_bfloat16* Ql0 = g_Qlo + (long)b*SEQ*DH;
        auto load_pro = [&](int ks) {
            load_kq(Kh0, Kl0, Qh0, Ql0, ks, ks % 3);
            uint32_t wb = sb + OB_WST + (uint32_t)(ks & 1)*16384u;
            int kb = ks * 64;
            #pragma unroll
            for (int p = 0; p < 4; p++) {
                int id = tid + p*256;
                int arr = id >> 9, rem = id & 511;
                int row = rem >> 3, ch = rem & 7;
                const __nv_bfloat16* src = (arr ? WloP : WhiP) + (long)row*DH + kb + ch*8;
                cp16(wb + arr*8192 + SW128((uint32_t)(row*128 + ch*16)), src);
            }
            CP_COMMIT();
        };
        load_pro(0);
        for (int ks = 0; ks < 16; ks++) {
            if (ks + 1 < 16) { load_pro(ks + 1); CP_WAIT(1); }
            else             { CP_WAIT(0); }
            __syncthreads();
            ph1_step(sb + OB_KQ + (uint32_t)(ks % 3)*32768u,
                     sb + OB_WST + (uint32_t)(ks & 1)*16384u);
            __syncthreads();
        }
    }

    for (int c = 0; c < NCH; c++) {
        const __nv_bfloat16* KhC = g_Khi + ((long)b*SEQ + c*CT)*DH;
        const __nv_bfloat16* KlC = g_Klo + ((long)b*SEQ + c*CT)*DH;
        const __nv_bfloat16* KhN = KhC + (long)CT*DH;
        const __nv_bfloat16* KlN = KlC + (long)CT*DH;
        const __nv_bfloat16* QhN = g_Qhi + ((long)b*SEQ + (c+1)*CT)*DH;
        const __nv_bfloat16* QlN = g_Qlo + ((long)b*SEQ + (c+1)*CT)*DH;
        const float* Vc  = g_V  + ((long)b*SEQ + c*CT)*DH;
        const float* gTi = g_Ti + (((long)b*NCH + c)*CT)*CT;
        const float* gMT = g_MT + (((long)b*NCH + c)*CT)*CT;
        int more = (c + 1 < NCH);

        __syncthreads();   // close previous merged loop / prologue

        // Ti/MT via cp.async (group), then next-chunk KQ stages 0,1 (groups)
        {
            #pragma unroll
            for (int p = 0; p < 8; p++) {
                int id = tid + p*256;
                int arr = id >> 10, rem = id & 1023;
                int s = rem >> 4, j = rem & 15;
                const float* src = (arr ? gMT : gTi) + s*64 + j*4;
                cp16(sb + (arr ? OB_MT : OB_TI) + (uint32_t)(s*272 + j*16), src);
            }
            CP_COMMIT();
        }
        if (more) {
            load_kq(KhN, KlN, QhN, QlN, 0, 0); CP_COMMIT();
            load_kq(KhN, KlN, QhN, QlN, 1, 1); CP_COMMIT();
        }

        // ---- phase-1 epilogue (c1 of chunk c) → U, P ----
        #pragma unroll
        for (int im = 0; im < 2; im++) {
            #pragma unroll
            for (int in = 0; in < 4; in++) {
                int rrow = wm + im*16 + grp;
                int n = wn + in*8 + t4*2;
                #pragma unroll
                for (int h = 0; h < 2; h++) {
                    int row2 = rrow + h*8;
                    float x0 = c1[im][in][h*2], x1 = c1[im][in][h*2+1];
                    if (row2 < 64) {
                        float2 vv = *(const float2*)(Vc + (long)row2*DH + r0 + n);
                        U[row2*68 + n]     = C2*(x0 + bsh[n]   - vv.x);
                        U[row2*68 + n + 1] = C2*(x1 + bsh[n+1] - vv.y);
                    } else {
                        P[(row2-64)*68 + n]     = x0 + bsh[n];
                        P[(row2-64)*68 + n + 1] = x1 + bsh[n+1];
                    }
                }
            }
        }
        if (more) { CP_WAIT(2); } else { CP_WAIT(0); }   // Ti/MT arrived
        __syncthreads();

        // ---- phase 2: G = Tinv @ U (f32x2) ----
        {
            ull ga[4][2];
            #pragma unroll
            for (int i = 0; i < 4; i++) { ga[i][0] = 0ull; ga[i][1] = 0ull; }
            #pragma unroll 4
            for (int s = 0; s < 64; s++) {
                float a[4];
                *(float4*)a = *(const float4*)(sTi + s*68 + ty*4);
                ulonglong2 bq = *(const ulonglong2*)(U + s*68 + tx*4);
                #pragma unroll
                for (int i = 0; i < 4; i++) {
                    ull aa = dupf(a[i]);
                    fma2(ga[i][0], aa, bq.x);
                    fma2(ga[i][1], aa, bq.y);
                }
            }
            #pragma unroll
            for (int i = 0; i < 4; i++) {
                int t = ty*4 + i;
                float2 c0 = unpack2(ga[i][0]), cq = unpack2(ga[i][1]);
                *(float4*)(G + t*68 + tx*4) = make_float4(c0.x, c0.y, cq.x, cq.y);
            }
        }
        __syncthreads();
        load_k4(KhC, KlC, 0, 0); CP_COMMIT();    // U dead → K4 buf0 OK

        // ---- phase 3: out = P - M~ @ G; Gt convert; bias ----
        {
            ull oa[4][2];
            #pragma unroll
            for (int i = 0; i < 4; i++) { oa[i][0] = 0ull; oa[i][1] = 0ull; }
            #pragma unroll 4
            for (int s = 0; s < 64; s++) {
                float a[4];
                *(float4*)a = *(const float4*)(sMT + s*68 + ty*4);
                ulonglong2 bq = *(const ulonglong2*)(G + s*68 + tx*4);
                #pragma unroll
                for (int i = 0; i < 4; i++) {
                    ull aa = dupf(a[i]);
                    fma2(oa[i][0], aa, bq.x);
                    fma2(oa[i][1], aa, bq.y);
                }
            }
            #pragma unroll
            for (int i = 0; i < 4; i++) {
                int t = ty*4 + i;
                float2 c0 = unpack2(oa[i][0]), cq = unpack2(oa[i][1]);
                float* op = out + ((long)b*SEQ + c*CT + t)*DH + r0 + tx*4;
                float4 pv = *(const float4*)(P + t*68 + tx*4);
                *(float4*)op = make_float4(pv.x - c0.x, pv.y - c0.y,
                                           pv.z - cq.x, pv.w - cq.y);
            }
            for (int idx = tid; idx < CT*CT; idx += 256) {
                int t_ = idx >> 6, r_ = idx & 63;
                float g = G[t_*68 + r_];
                __nv_bfloat16 h = __float2bfloat16(g);
                float hf = __bfloat162float(h);
                __nv_bfloat16 l = __float2bfloat16(g - hf);
                uint32_t off = SW128((uint32_t)(r_*128 + t_*2));
                *(__nv_bfloat16*)(smc + OB_GTH + off) = h;
                *(__nv_bfloat16*)(smc + OB_GTL + off) = l;
            }
            if (tid < 64) {
                float sumg = 0.f;
                #pragma unroll 8
                for (int t = 0; t < 64; t++) sumg += G[t*68 + tid];
                bsh[tid] -= LRATE * sumg;
            }
        }
        __syncthreads();
        load_k4(KhC, KlC, 1, 1); CP_COMMIT();    // P, G dead

        // preload invariant A-fragments (G^T hi/lo)
        #pragma unroll
        for (int kk = 0; kk < 4; kk++) {
            int t = lane >> 3, ri = lane & 7;
            int row = wm4 + (t & 1)*8 + ri;
            uint32_t off = SW128((uint32_t)(row*128 + kk*32 + (t >> 1)*16));
            ldsm_x4(afh[kk], gth + off);
            ldsm_x4(afl[kk], gtl + off);
        }

        if (more) {
            // ===== merged: ph4(c) tile jt ∥ ph1(c+1) stage jt =====
            #pragma unroll
            for (int im = 0; im < 2; im++)
                #pragma unroll
                for (int in = 0; in < 4; in++)
                    #pragma unroll
                    for (int k = 0; k < 4; k++) c1[im][in][k] = 0.f;

            float2 wcur[4][2];
            #pragma unroll
            for (int in = 0; in < 4; in++)
                #pragma unroll
                for (int h = 0; h < 2; h++)
                    wcur[in][h] = *(float2*)(Wp + (long)(wm4 + grp + h*8)*DH
                                             + wn4 + in*8 + t4*2);

            for (int jt = 0; jt < 16; jt++) {
                if (jt == 0)      { CP_WAIT(1); }
                else if (jt < 15) { CP_WAIT(2); }
                else              { CP_WAIT(0); }
                __syncthreads();
                if (jt + 2 < 16) {
                    load_kq(KhN, KlN, QhN, QlN, jt + 2, (jt + 2) % 3); CP_COMMIT();
                    load_k4(KhC, KlC, jt + 2, (jt + 2) % 3);           CP_COMMIT();
                }

                float c4[4][4];
                ph4_step(sb + OB_K4 + (uint32_t)(jt % 3)*16384u, c4);

                // epilogue: W update → fp32 global + bf16 hi/lo → Wst[jt&1]
                uint32_t wst = sb + OB_WST + (uint32_t)(jt & 1)*16384u;
                #pragma unroll
                for (int in = 0; in < 4; in++) {
                    int lc = wn4 + in*8 + t4*2;          // local col 0..63
                    #pragma unroll
                    for (int h = 0; h < 2; h++) {
                        int rw = wm4 + grp + h*8;
                        float wx = wcur[in][h].x - LRATE * c4[in][h*2+0];
                        float wy = wcur[in][h].y - LRATE * c4[in][h*2+1];
                        *(float2*)(Wp + (long)rw*DH + jt*64 + lc) = make_float2(wx, wy);
                        __nv_bfloat16 h0 = __float2bfloat16(wx);
                        __nv_bfloat16 h1 = __float2bfloat16(wy);
                        __nv_bfloat162 hv; hv.x = h0; hv.y = h1;
                        __nv_bfloat162 lv;
                        lv.x = __float2bfloat16(wx - __bfloat162float(h0));
                        lv.y = __float2bfloat16(wy - __bfloat162float(h1));
                        uint32_t off = SW128((uint32_t)(rw*128 + lc*2));
                        *(__nv_bfloat162*)(smc + (wst - sb) + off)        = hv;
                        *(__nv_bfloat162*)(smc + (wst - sb) + 8192 + off) = lv;
                    }
                }
                if (jt < 15) {      // prefetch next W tile (fp32) into regs
                    #pragma unroll
                    for (int in = 0; in < 4; in++)
                        #pragma unroll
                        for (int h = 0; h < 2; h++)
                            wcur[in][h] = *(float2*)(Wp + (long)(wm4 + grp + h*8)*DH
                                                     + (jt+1)*64 + wn4 + in*8 + t4*2);
                }
                __syncthreads();
                ph1_step(sb + OB_KQ + (uint32_t)(jt % 3)*32768u, wst);
            }
        } else {
            // ===== final chunk: phase 4 only (fp32 W RMW, no handoff) =====
            for (int jt = 0; jt < 16; jt++) {
                if (jt < 15) { CP_WAIT(1); } else { CP_WAIT(0); }
                __syncthreads();
                if (jt + 2 < 16) { load_k4(KhC, KlC, jt + 2, (jt + 2) % 3); CP_COMMIT(); }

                float c4[4][4];
                ph4_step(sb + OB_K4 + (uint32_t)(jt % 3)*16384u, c4);

                #pragma unroll
                for (int in = 0; in < 4; in++) {
                    int colg = jt*64 + wn4 + in*8 + t4*2;
                    #pragma unroll
                    for (int h = 0; h < 2; h++) {
                        int rw = wm4 + grp + h*8;
                        long idx = (long)rw*DH + colg;
                        float2 w = *(float2*)(Wp + idx);
                        w.x -= LRATE * c4[in][h*2+0];
                        w.y -= LRATE * c4[in][h*2+1];
                        *(float2*)(Wp + idx) = w;
                    }
                }
            }
        }
    }
}

// ---------------- launch ------------------------------------------------------
extern "C" void kernel_launch(void* const* d_in, const int* in_sizes, int n_in,
                              void* d_out, int out_size) {
    const float* in_seq = (const float*)d_in[0];
    const float* tK = (const float*)d_in[1];
    const float* tV = (const float*)d_in[2];
    const float* tQ = (const float*)d_in[3];
    const float* W0 = (const float*)d_in[4];
    const float* b0 = (const float*)d_in[5];
    float* out = (float*)d_out;

    cudaFuncSetAttribute(chunk_fused_kernel,
                         cudaFuncAttributeMaxDynamicSharedMemorySize, CH_SMEM);
    cudaFuncSetAttribute(proj_mma_kernel,
                         cudaFuncAttributeMaxDynamicSharedMemorySize, PROJ_SMEM);
    cudaFuncSetAttribute(am_mma_kernel,
                         cudaFuncAttributeMaxDynamicSharedMemorySize, AM_SMEM);

    cvt_kernel<<<(NB*SEQ*DH)/256, 256>>>(in_seq, tK, tV, tQ);
    init_state_kernel<<<(DH*DH)/256, 256>>>(W0);
    proj_mma_kernel<<<dim3((NB*SEQ)/128, DH/64, 3), 256, PROJ_SMEM>>>();
    am_mma_kernel<<<dim3(NCH, NB), 256, AM_SMEM>>>();
    tinv_kernel<<<dim3(NCH, NB), 64>>>();
    chunk_fused_kernel<<<dim3(DH/64, NB), 256, CH_SMEM>>>(out, b0);
}